// round 1
// baseline (speedup 1.0000x reference)
#include <cuda_runtime.h>
#include <math.h>

// Problem constants
#define BB 4
#define TT 1024
#define CC 1024
#define HH 16
#define DD 64
#define RR 8
#define MTOK (BB*TT)        // 4096
#define NQKV (3*CC)         // 3072
#define LORA_SCALE 2.0f     // 16 / 8

// Scratch (allocation-free rule: __device__ globals)
__device__ float g_qkv[MTOK * NQKV];   // [4096, 3072]
__device__ float g_y[MTOK * CC];       // [4096, 1024]
__device__ float g_tmpa[MTOK * RR];    // x @ la_attn^T
__device__ float g_tmpp[MTOK * RR];    // y @ la_proj^T

// ---------------------------------------------------------------------------
// Kernel 1: rank-R LoRA vector:  out[row, r] = sum_k X[row,k] * LA[r,k]
// One block per row; warp w computes rank r=w. blockDim = 256 (8 warps = R).
// mode 0: X = Xin, out = g_tmpa ; mode 1: X = g_y, out = g_tmpp
// ---------------------------------------------------------------------------
__global__ __launch_bounds__(256)
void lora_vec_kernel(const float* __restrict__ Xin, const float* __restrict__ LA, int mode) {
    const float* X  = (mode == 0) ? Xin : g_y;
    float* out      = (mode == 0) ? g_tmpa : g_tmpp;
    int row  = blockIdx.x;
    int warp = threadIdx.x >> 5;
    int lane = threadIdx.x & 31;
    const float* xr = X + (size_t)row * CC;
    const float* lr = LA + (size_t)warp * CC;
    float s = 0.f;
    #pragma unroll 8
    for (int k = lane; k < CC; k += 32) s += xr[k] * lr[k];
    #pragma unroll
    for (int o = 16; o > 0; o >>= 1) s += __shfl_xor_sync(0xffffffffu, s, o);
    if (lane == 0) out[row * RR + warp] = s;
}

// ---------------------------------------------------------------------------
// Kernel 2: fused GEMM + LoRA epilogue + bias
//   OUT[M,N] = X[M,K] @ W[N,K]^T + LORA_SCALE * TMP[M,R] @ LB[N,R]^T + bias[N]
// Tiles: 64x64x16, 256 threads, 4x4 per-thread micro-tile. M=4096, K=1024 fixed.
// mode 0: X=Xin, OUT=g_qkv, TMP=g_tmpa (N=3072)
// mode 1: X=g_y, OUT=Oout,  TMP=g_tmpp (N=1024)
// ---------------------------------------------------------------------------
__global__ __launch_bounds__(256)
void gemm_lora_kernel(const float* __restrict__ Xin,
                      const float* __restrict__ W,
                      const float* __restrict__ LB,
                      const float* __restrict__ bias,
                      float* __restrict__ Oout,
                      int mode, int N) {
    const int K = CC;  // 1024
    const float* X   = (mode == 0) ? Xin : g_y;
    float*       OUT = (mode == 0) ? g_qkv : Oout;
    const float* TMP = (mode == 0) ? g_tmpa : g_tmpp;

    __shared__ float As[16][64];
    __shared__ float Ws[16][64];

    int tx = threadIdx.x & 15;   // 0..15 -> 4 output cols
    int ty = threadIdx.x >> 4;   // 0..15 -> 4 output rows
    int row0 = blockIdx.y * 64;
    int col0 = blockIdx.x * 64;

    float acc[4][4] = {};

    int li = threadIdx.x * 4;
    int lm = li >> 4;       // 0..63 tile row
    int lk = li & 15;       // 0,4,8,12

    for (int k0 = 0; k0 < K; k0 += 16) {
        float4 xa = *(const float4*)(X + (size_t)(row0 + lm) * K + k0 + lk);
        float4 wa = *(const float4*)(W + (size_t)(col0 + lm) * K + k0 + lk);
        __syncthreads();   // protect previous iteration's reads
        As[lk+0][lm] = xa.x; As[lk+1][lm] = xa.y; As[lk+2][lm] = xa.z; As[lk+3][lm] = xa.w;
        Ws[lk+0][lm] = wa.x; Ws[lk+1][lm] = wa.y; Ws[lk+2][lm] = wa.z; Ws[lk+3][lm] = wa.w;
        __syncthreads();
        #pragma unroll
        for (int kk = 0; kk < 16; kk++) {
            float a[4], b[4];
            #pragma unroll
            for (int i = 0; i < 4; i++) a[i] = As[kk][ty*4 + i];
            #pragma unroll
            for (int j = 0; j < 4; j++) b[j] = Ws[kk][tx*4 + j];
            #pragma unroll
            for (int i = 0; i < 4; i++)
                #pragma unroll
                for (int j = 0; j < 4; j++)
                    acc[i][j] += a[i] * b[j];
        }
    }

    // Epilogue: bias + LoRA rank-8 outer-product contribution
    float tl[4][RR], lbv[4][RR], bj[4];
    #pragma unroll
    for (int i = 0; i < 4; i++) {
        int row = row0 + ty*4 + i;
        #pragma unroll
        for (int r = 0; r < RR; r++) tl[i][r] = TMP[row*RR + r];
    }
    #pragma unroll
    for (int j = 0; j < 4; j++) {
        int col = col0 + tx*4 + j;
        bj[j] = bias[col];
        #pragma unroll
        for (int r = 0; r < RR; r++) lbv[j][r] = LB[col*RR + r];
    }
    #pragma unroll
    for (int i = 0; i < 4; i++) {
        int row = row0 + ty*4 + i;
        #pragma unroll
        for (int j = 0; j < 4; j++) {
            int col = col0 + tx*4 + j;
            float d8 = 0.f;
            #pragma unroll
            for (int r = 0; r < RR; r++) d8 += tl[i][r] * lbv[j][r];
            OUT[(size_t)row * N + col] = acc[i][j] + bj[j] + LORA_SCALE * d8;
        }
    }
}

// ---------------------------------------------------------------------------
// Kernel 3: causal attention (flash-style, online softmax)
// Block: 256 threads = 8 warps = 8 consecutive query rows of one (b,h).
// Grid: (T/8, B*H). K/V staged per 32-key chunk into padded smem.
// Reproduces reference nan_to_num(-inf) semantics: pad-masked (k<=q) keys get
// score -3e38 (finite), causal-out keys excluded (exp underflows to 0 anyway).
// ---------------------------------------------------------------------------
__global__ __launch_bounds__(256)
void attn_kernel(const int* __restrict__ pad) {
    __shared__ float Ks[32][65];
    __shared__ float Vs[32][65];
    __shared__ float Qs[8][64];

    int warp = threadIdx.x >> 5;
    int lane = threadIdx.x & 31;
    int bh = blockIdx.y;
    int b = bh / HH, h = bh % HH;
    int q0 = blockIdx.x * 8;
    int qrow = q0 + warp;

    // Load+scale 8 Q rows into smem
    for (int e = threadIdx.x; e < 8*64; e += 256) {
        int r = e >> 6, d = e & 63;
        Qs[r][d] = g_qkv[(size_t)(b*TT + q0 + r) * NQKV + h*DD + d] * 0.125f; // 1/sqrt(64)
    }

    float m = -INFINITY, ssum = 0.f, acc0 = 0.f, acc1 = 0.f;
    const int q_max_blk = q0 + 7;
    const int* padrow = pad + (size_t)b * TT * TT + (size_t)qrow * TT;

    int ldr  = threadIdx.x >> 3;          // 0..31  chunk row
    int ldd  = (threadIdx.x & 7) * 8;     // 0..56  chunk col (8 floats)

    for (int k0 = 0; k0 <= q_max_blk; k0 += 32) {
        __syncthreads();  // protect previous chunk reads (also covers Qs stores on iter 0)
        {
            const float* srck = g_qkv + (size_t)(b*TT + k0 + ldr) * NQKV + CC + h*DD + ldd;
            float4 a0 = *(const float4*)(srck);
            float4 a1 = *(const float4*)(srck + 4);
            const float* srcv = srck + CC;
            float4 b0 = *(const float4*)(srcv);
            float4 b1 = *(const float4*)(srcv + 4);
            Ks[ldr][ldd+0]=a0.x; Ks[ldr][ldd+1]=a0.y; Ks[ldr][ldd+2]=a0.z; Ks[ldr][ldd+3]=a0.w;
            Ks[ldr][ldd+4]=a1.x; Ks[ldr][ldd+5]=a1.y; Ks[ldr][ldd+6]=a1.z; Ks[ldr][ldd+7]=a1.w;
            Vs[ldr][ldd+0]=b0.x; Vs[ldr][ldd+1]=b0.y; Vs[ldr][ldd+2]=b0.z; Vs[ldr][ldd+3]=b0.w;
            Vs[ldr][ldd+4]=b1.x; Vs[ldr][ldd+5]=b1.y; Vs[ldr][ldd+6]=b1.z; Vs[ldr][ldd+7]=b1.w;
        }
        __syncthreads();

        if (k0 <= qrow) {
            int kt = k0 + lane;
            float dsum = 0.f;
            #pragma unroll 16
            for (int j = 0; j < 64; j++) dsum += Qs[warp][j] * Ks[lane][j];
            bool in_range = (kt <= qrow);
            bool pad_ok   = in_range && (padrow[kt] != 0);
            float score = pad_ok ? dsum : (in_range ? -3.0e38f : -INFINITY);

            float mx = score;
            #pragma unroll
            for (int o = 16; o > 0; o >>= 1) mx = fmaxf(mx, __shfl_xor_sync(0xffffffffu, mx, o));
            float mnew = fmaxf(m, mx);
            float corr = __expf(m - mnew);
            float p = __expf(score - mnew);

            float psum = p;
            #pragma unroll
            for (int o = 16; o > 0; o >>= 1) psum += __shfl_xor_sync(0xffffffffu, psum, o);
            ssum = ssum * corr + psum;
            acc0 *= corr; acc1 *= corr;
            #pragma unroll
            for (int j = 0; j < 32; j++) {
                float pj = __shfl_sync(0xffffffffu, p, j);
                acc0 += pj * Vs[j][lane];
                acc1 += pj * Vs[j][lane + 32];
            }
            m = mnew;
        }
    }

    float inv = 1.0f / ssum;
    size_t yoff = (size_t)(b*TT + qrow) * CC + h*DD;
    g_y[yoff + lane]      = acc0 * inv;
    g_y[yoff + lane + 32] = acc1 * inv;
}

// ---------------------------------------------------------------------------
extern "C" void kernel_launch(void* const* d_in, const int* in_sizes, int n_in,
                              void* d_out, int out_size) {
    const float* x       = (const float*)d_in[0];
    const int*   pad     = (const int*)  d_in[1];
    const float* attn_w  = (const float*)d_in[2];
    const float* attn_b  = (const float*)d_in[3];
    const float* la_attn = (const float*)d_in[4];
    const float* lb_attn = (const float*)d_in[5];
    const float* proj_w  = (const float*)d_in[6];
    const float* proj_b  = (const float*)d_in[7];
    const float* la_proj = (const float*)d_in[8];
    const float* lb_proj = (const float*)d_in[9];
    float* out = (float*)d_out;

    // 1. tmpa = x @ la_attn^T
    lora_vec_kernel<<<MTOK, 256>>>(x, la_attn, 0);
    // 2. qkv = x @ c_attn_w^T + 2*tmpa @ lb_attn^T + b
    gemm_lora_kernel<<<dim3(NQKV/64, MTOK/64), 256>>>(x, attn_w, lb_attn, attn_b, nullptr, 0, NQKV);
    // 3. attention -> g_y
    attn_kernel<<<dim3(TT/8, BB*HH), 256>>>(pad);
    // 4. tmpp = y @ la_proj^T
    lora_vec_kernel<<<MTOK, 256>>>(nullptr, la_proj, 1);
    // 5. out = y @ c_proj_w^T + 2*tmpp @ lb_proj^T + b
    gemm_lora_kernel<<<dim3(CC/64, MTOK/64), 256>>>(nullptr, proj_w, lb_proj, proj_b, out, 1, CC);
}

// round 2
// speedup vs baseline: 1.2596x; 1.2596x over previous
#include <cuda_runtime.h>
#include <mma.h>
#include <math.h>

using namespace nvcuda;

// Problem constants
#define BB 4
#define TT 1024
#define CC 1024
#define HH 16
#define DD 64
#define RR 8
#define MTOK (BB*TT)        // 4096
#define NQKV (3*CC)         // 3072
#define LORA_SCALE 2.0f     // 16 / 8

// GEMM tiling
#define BM 128
#define BN 64
#define BK 16
#define BKP 20              // padded ld for A/B smem (20*4B = 80B, 16B-aligned rows)
#define BNP 68              // padded ld for C smem

// Scratch (allocation-free rule: __device__ globals)
__device__ float g_qkv[MTOK * NQKV];   // [4096, 3072]
__device__ float g_y[MTOK * CC];       // [4096, 1024]
__device__ float g_tmpa[MTOK * RR];    // x @ la_attn^T
__device__ float g_tmpp[MTOK * RR];    // y @ la_proj^T

// ---------------------------------------------------------------------------
// Kernel 1: rank-R LoRA vector:  out[row, r] = sum_k X[row,k] * LA[r,k]
// ---------------------------------------------------------------------------
__global__ __launch_bounds__(256)
void lora_vec_kernel(const float* __restrict__ Xin, const float* __restrict__ LA, int mode) {
    const float* X  = (mode == 0) ? Xin : g_y;
    float* out      = (mode == 0) ? g_tmpa : g_tmpp;
    int row  = blockIdx.x;
    int warp = threadIdx.x >> 5;
    int lane = threadIdx.x & 31;
    const float* xr = X + (size_t)row * CC;
    const float* lr = LA + (size_t)warp * CC;
    float s = 0.f;
    #pragma unroll 8
    for (int k = lane; k < CC; k += 32) s += xr[k] * lr[k];
    #pragma unroll
    for (int o = 16; o > 0; o >>= 1) s += __shfl_xor_sync(0xffffffffu, s, o);
    if (lane == 0) out[row * RR + warp] = s;
}

// ---------------------------------------------------------------------------
// Kernel 2: tf32 tensor-core GEMM + LoRA epilogue + bias
//   OUT[M,N] = X[M,K] @ W[N,K]^T + LORA_SCALE * TMP[M,R] @ LB[N,R]^T + bias[N]
// Block tile 128x64, BK=16. 8 warps (4 along M, 2 along N), each warp 32x32
// via 2x2 wmma m16n16k8 tf32 fragments. W row-major [N,K] is exactly the
// col-major B operand. C staged in smem (union with A/B tiles) for epilogue.
// ---------------------------------------------------------------------------
__global__ __launch_bounds__(256)
void gemm_lora_tf32(const float* __restrict__ Xin,
                    const float* __restrict__ W,
                    const float* __restrict__ LB,
                    const float* __restrict__ bias,
                    float* __restrict__ Oout,
                    int mode, int N) {
    const int K = CC;  // 1024
    const float* X   = (mode == 0) ? Xin : g_y;
    float*       OUT = (mode == 0) ? g_qkv : Oout;
    const float* TMP = (mode == 0) ? g_tmpa : g_tmpp;

    __shared__ union {
        struct { float As[BM][BKP]; float Bs[BN][BKP]; } ab;   // 15.4 KB
        float Cs[BM][BNP];                                     // 34.8 KB
    } sh;

    int tid   = threadIdx.x;
    int warp  = tid >> 5;
    int wm    = warp & 3;          // 0..3 -> M offset warp
    int wn    = warp >> 2;         // 0..1 -> N offset warp
    int row0  = blockIdx.y * BM;
    int col0  = blockIdx.x * BN;

    wmma::fragment<wmma::accumulator, 16, 16, 8, float> acc[2][2];
    #pragma unroll
    for (int i = 0; i < 2; i++)
        #pragma unroll
        for (int j = 0; j < 2; j++) wmma::fill_fragment(acc[i][j], 0.0f);

    // Global load mapping
    // A tile: 128x16 = 512 float4 -> 2 per thread
    int af = tid * 2;
    int ar0 = af >> 2,       ac0 = (af & 3) * 4;          // float4 #1
    int ar1 = (af + 1) >> 2, ac1 = ((af + 1) & 3) * 4;    // float4 #2
    // B tile: 64x16 = 256 float4 -> 1 per thread
    int br = tid >> 2, bc = (tid & 3) * 4;

    const float* Abase = X + (size_t)row0 * K;
    const float* Bbase = W + (size_t)col0 * K;

    for (int k0 = 0; k0 < K; k0 += BK) {
        float4 xa0 = *(const float4*)(Abase + (size_t)ar0 * K + k0 + ac0);
        float4 xa1 = *(const float4*)(Abase + (size_t)ar1 * K + k0 + ac1);
        float4 wb  = *(const float4*)(Bbase + (size_t)br  * K + k0 + bc);
        __syncthreads();  // protect previous iteration's fragment reads
        *(float4*)&sh.ab.As[ar0][ac0] = xa0;
        *(float4*)&sh.ab.As[ar1][ac1] = xa1;
        *(float4*)&sh.ab.Bs[br][bc]   = wb;
        __syncthreads();

        #pragma unroll
        for (int ks = 0; ks < BK; ks += 8) {
            wmma::fragment<wmma::matrix_a, 16, 16, 8, wmma::precision::tf32, wmma::row_major> fa[2];
            wmma::fragment<wmma::matrix_b, 16, 16, 8, wmma::precision::tf32, wmma::col_major> fb[2];
            #pragma unroll
            for (int i = 0; i < 2; i++) {
                wmma::load_matrix_sync(fa[i], &sh.ab.As[wm*32 + i*16][ks], BKP);
                #pragma unroll
                for (int e = 0; e < fa[i].num_elements; e++)
                    fa[i].x[e] = wmma::__float_to_tf32(fa[i].x[e]);
            }
            #pragma unroll
            for (int j = 0; j < 2; j++) {
                wmma::load_matrix_sync(fb[j], &sh.ab.Bs[wn*32 + j*16][ks], BKP);
                #pragma unroll
                for (int e = 0; e < fb[j].num_elements; e++)
                    fb[j].x[e] = wmma::__float_to_tf32(fb[j].x[e]);
            }
            #pragma unroll
            for (int i = 0; i < 2; i++)
                #pragma unroll
                for (int j = 0; j < 2; j++)
                    wmma::mma_sync(acc[i][j], fa[i], fb[j], acc[i][j]);
        }
    }

    // Stage C to smem (union: A/B tiles dead now)
    __syncthreads();
    #pragma unroll
    for (int i = 0; i < 2; i++)
        #pragma unroll
        for (int j = 0; j < 2; j++)
            wmma::store_matrix_sync(&sh.Cs[wm*32 + i*16][wn*32 + j*16], acc[i][j],
                                    BNP, wmma::mem_row_major);
    __syncthreads();

    // Epilogue: bias + rank-8 LoRA. 128*64/256 = 32 elements per thread.
    #pragma unroll 4
    for (int e = tid; e < BM * BN; e += 256) {
        int r = e >> 6;          // 0..127 (BN=64)
        int c = e & 63;
        int grow = row0 + r;
        int gcol = col0 + c;
        const float* tl  = TMP + grow * RR;
        const float* lbv = LB + (size_t)gcol * RR;
        float d8 = 0.f;
        #pragma unroll
        for (int q = 0; q < RR; q++) d8 += tl[q] * lbv[q];
        OUT[(size_t)grow * N + gcol] = sh.Cs[r][c] + bias[gcol] + LORA_SCALE * d8;
    }
}

// ---------------------------------------------------------------------------
// Kernel 3: causal attention (flash-style, online softmax) — unchanged
// ---------------------------------------------------------------------------
__global__ __launch_bounds__(256)
void attn_kernel(const int* __restrict__ pad) {
    __shared__ float Ks[32][65];
    __shared__ float Vs[32][65];
    __shared__ float Qs[8][64];

    int warp = threadIdx.x >> 5;
    int lane = threadIdx.x & 31;
    int bh = blockIdx.y;
    int b = bh / HH, h = bh % HH;
    int q0 = blockIdx.x * 8;
    int qrow = q0 + warp;

    for (int e = threadIdx.x; e < 8*64; e += 256) {
        int r = e >> 6, d = e & 63;
        Qs[r][d] = g_qkv[(size_t)(b*TT + q0 + r) * NQKV + h*DD + d] * 0.125f; // 1/sqrt(64)
    }

    float m = -INFINITY, ssum = 0.f, acc0 = 0.f, acc1 = 0.f;
    const int q_max_blk = q0 + 7;
    const int* padrow = pad + (size_t)b * TT * TT + (size_t)qrow * TT;

    int ldr  = threadIdx.x >> 3;          // 0..31  chunk row
    int ldd  = (threadIdx.x & 7) * 8;     // 0..56  chunk col (8 floats)

    for (int k0 = 0; k0 <= q_max_blk; k0 += 32) {
        __syncthreads();
        {
            const float* srck = g_qkv + (size_t)(b*TT + k0 + ldr) * NQKV + CC + h*DD + ldd;
            float4 a0 = *(const float4*)(srck);
            float4 a1 = *(const float4*)(srck + 4);
            const float* srcv = srck + CC;
            float4 b0 = *(const float4*)(srcv);
            float4 b1 = *(const float4*)(srcv + 4);
            Ks[ldr][ldd+0]=a0.x; Ks[ldr][ldd+1]=a0.y; Ks[ldr][ldd+2]=a0.z; Ks[ldr][ldd+3]=a0.w;
            Ks[ldr][ldd+4]=a1.x; Ks[ldr][ldd+5]=a1.y; Ks[ldr][ldd+6]=a1.z; Ks[ldr][ldd+7]=a1.w;
            Vs[ldr][ldd+0]=b0.x; Vs[ldr][ldd+1]=b0.y; Vs[ldr][ldd+2]=b0.z; Vs[ldr][ldd+3]=b0.w;
            Vs[ldr][ldd+4]=b1.x; Vs[ldr][ldd+5]=b1.y; Vs[ldr][ldd+6]=b1.z; Vs[ldr][ldd+7]=b1.w;
        }
        __syncthreads();

        if (k0 <= qrow) {
            int kt = k0 + lane;
            float dsum = 0.f;
            #pragma unroll 16
            for (int j = 0; j < 64; j++) dsum += Qs[warp][j] * Ks[lane][j];
            bool in_range = (kt <= qrow);
            bool pad_ok   = in_range && (padrow[kt] != 0);
            float score = pad_ok ? dsum : (in_range ? -3.0e38f : -INFINITY);

            float mx = score;
            #pragma unroll
            for (int o = 16; o > 0; o >>= 1) mx = fmaxf(mx, __shfl_xor_sync(0xffffffffu, mx, o));
            float mnew = fmaxf(m, mx);
            float corr = __expf(m - mnew);
            float p = __expf(score - mnew);

            float psum = p;
            #pragma unroll
            for (int o = 16; o > 0; o >>= 1) psum += __shfl_xor_sync(0xffffffffu, psum, o);
            ssum = ssum * corr + psum;
            acc0 *= corr; acc1 *= corr;
            #pragma unroll
            for (int j = 0; j < 32; j++) {
                float pj = __shfl_sync(0xffffffffu, p, j);
                acc0 += pj * Vs[j][lane];
                acc1 += pj * Vs[j][lane + 32];
            }
            m = mnew;
        }
    }

    float inv = 1.0f / ssum;
    size_t yoff = (size_t)(b*TT + qrow) * CC + h*DD;
    g_y[yoff + lane]      = acc0 * inv;
    g_y[yoff + lane + 32] = acc1 * inv;
}

// ---------------------------------------------------------------------------
extern "C" void kernel_launch(void* const* d_in, const int* in_sizes, int n_in,
                              void* d_out, int out_size) {
    const float* x       = (const float*)d_in[0];
    const int*   pad     = (const int*)  d_in[1];
    const float* attn_w  = (const float*)d_in[2];
    const float* attn_b  = (const float*)d_in[3];
    const float* la_attn = (const float*)d_in[4];
    const float* lb_attn = (const float*)d_in[5];
    const float* proj_w  = (const float*)d_in[6];
    const float* proj_b  = (const float*)d_in[7];
    const float* la_proj = (const float*)d_in[8];
    const float* lb_proj = (const float*)d_in[9];
    float* out = (float*)d_out;

    // 1. tmpa = x @ la_attn^T
    lora_vec_kernel<<<MTOK, 256>>>(x, la_attn, 0);
    // 2. qkv = x @ c_attn_w^T + 2*tmpa @ lb_attn^T + b
    gemm_lora_tf32<<<dim3(NQKV/BN, MTOK/BM), 256>>>(x, attn_w, lb_attn, attn_b, nullptr, 0, NQKV);
    // 3. attention -> g_y
    attn_kernel<<<dim3(TT/8, BB*HH), 256>>>(pad);
    // 4. tmpp = y @ la_proj^T
    lora_vec_kernel<<<MTOK, 256>>>(nullptr, la_proj, 1);
    // 5. out = y @ c_proj_w^T + 2*tmpp @ lb_proj^T + b
    gemm_lora_tf32<<<dim3(CC/BN, MTOK/BM), 256>>>(nullptr, proj_w, lb_proj, proj_b, out, 1, CC);
}

// round 4
// speedup vs baseline: 1.2653x; 1.0046x over previous
#include <cuda_runtime.h>
#include <mma.h>
#include <math.h>
#include <cstdint>

using namespace nvcuda;

// Problem constants
#define BB 4
#define TT 1024
#define CC 1024
#define HH 16
#define DD 64
#define RR 8
#define MTOK (BB*TT)        // 4096
#define NQKV (3*CC)         // 3072
#define LORA_SCALE 2.0f     // 16 / 8

// GEMM tiling
#define BM 128
#define BN 128
#define BK 32
#define BKP 36              // padded smem ld (36*4B, 16B-aligned rows)
#define CNP 132             // padded C staging ld
#define NK (CC/BK)          // 32 K-iterations
#define GEMM_SMEM (2*(BM+BN)*BKP*4)   // 73728 bytes

// Scratch (allocation-free rule: __device__ globals)
__device__ float g_qkv[MTOK * NQKV];   // [4096, 3072]
__device__ float g_y[MTOK * CC];       // [4096, 1024]
__device__ float g_tmpa[MTOK * RR];
__device__ float g_tmpp[MTOK * RR];

__device__ __forceinline__ void cp_async16(void* sptr, const void* gptr) {
    unsigned int sa = (unsigned int)__cvta_generic_to_shared(sptr);
    asm volatile("cp.async.cg.shared.global [%0], [%1], 16;\n" :: "r"(sa), "l"(gptr));
}

// ---------------------------------------------------------------------------
// Kernel 1: rank-R LoRA vector:  out[row, r] = sum_k X[row,k] * LA[r,k]
// ---------------------------------------------------------------------------
__global__ __launch_bounds__(256)
void lora_vec_kernel(const float* __restrict__ Xin, const float* __restrict__ LA, int mode) {
    const float* X  = (mode == 0) ? Xin : g_y;
    float* out      = (mode == 0) ? g_tmpa : g_tmpp;
    int row  = blockIdx.x;
    int warp = threadIdx.x >> 5;
    int lane = threadIdx.x & 31;
    const float* xr = X + (size_t)row * CC;
    const float* lr = LA + (size_t)warp * CC;
    float s = 0.f;
    #pragma unroll 8
    for (int k = lane; k < CC; k += 32) s += xr[k] * lr[k];
    #pragma unroll
    for (int o = 16; o > 0; o >>= 1) s += __shfl_xor_sync(0xffffffffu, s, o);
    if (lane == 0) out[row * RR + warp] = s;
}

// ---------------------------------------------------------------------------
// Kernel 2: tf32 tensor-core GEMM, cp.async double-buffered, + LoRA + bias
//   OUT[M,N] = X[M,K] @ W[N,K]^T + LORA_SCALE * TMP[M,R] @ LB[N,R]^T + bias[N]
// 128x128x32 tile, 8 warps (2 M x 4 N), warp tile 64x32 (4x2 wmma 16x16k8).
// ---------------------------------------------------------------------------
__global__ __launch_bounds__(256)
void gemm_lora_tf32(const float* __restrict__ Xin,
                    const float* __restrict__ W,
                    const float* __restrict__ LB,
                    const float* __restrict__ bias,
                    float* __restrict__ Oout,
                    int mode, int N) {
    const int K = CC;
    const float* X   = (mode == 0) ? Xin : g_y;
    float*       OUT = (mode == 0) ? g_qkv : Oout;
    const float* TMP = (mode == 0) ? g_tmpa : g_tmpp;

    extern __shared__ float smem[];
    float* As = smem;                          // [2][BM][BKP]
    float* Bs = smem + 2 * BM * BKP;           // [2][BN][BKP]

    int tid  = threadIdx.x;
    int warp = tid >> 5;
    int wm   = warp >> 2;        // 0..1  -> M offset wm*64
    int wn   = warp & 3;         // 0..3  -> N offset wn*32
    int row0 = blockIdx.y * BM;
    int col0 = blockIdx.x * BN;

    // Global->smem mapping: per stage, A is 128x32 floats = 1024 float4,
    // 4 per thread (rows t>>3 + 32j, col (t&7)*4). Same shape for B.
    int lrow = tid >> 3;            // 0..31
    int lcol = (tid & 7) * 4;       // 0,4,...,28
    const float* Abase = X + (size_t)(row0 + lrow) * K + lcol;
    const float* Bbase = W + (size_t)(col0 + lrow) * K + lcol;

    wmma::fragment<wmma::accumulator, 16, 16, 8, float> acc[4][2];
    #pragma unroll
    for (int i = 0; i < 4; i++)
        #pragma unroll
        for (int j = 0; j < 2; j++) wmma::fill_fragment(acc[i][j], 0.0f);

    // Prologue: stage 0 loads
    {
        float* Ad = As + lrow * BKP + lcol;
        float* Bd = Bs + lrow * BKP + lcol;
        #pragma unroll
        for (int j = 0; j < 4; j++) {
            cp_async16(Ad + j * 32 * BKP, Abase + (size_t)(32 * j) * K);
            cp_async16(Bd + j * 32 * BKP, Bbase + (size_t)(32 * j) * K);
        }
        asm volatile("cp.async.commit_group;\n");
    }

    for (int it = 0; it < NK; ++it) {
        if (it + 1 < NK) {
            int s = (it + 1) & 1;
            int k0 = (it + 1) * BK;
            float* Ad = As + s * BM * BKP + lrow * BKP + lcol;
            float* Bd = Bs + s * BN * BKP + lrow * BKP + lcol;
            #pragma unroll
            for (int j = 0; j < 4; j++) {
                cp_async16(Ad + j * 32 * BKP, Abase + (size_t)(32 * j) * K + k0);
                cp_async16(Bd + j * 32 * BKP, Bbase + (size_t)(32 * j) * K + k0);
            }
            asm volatile("cp.async.commit_group;\n");
            asm volatile("cp.async.wait_group 1;\n");
        } else {
            asm volatile("cp.async.wait_group 0;\n");
        }
        __syncthreads();

        int s = it & 1;
        const float* Asv = As + s * BM * BKP;
        const float* Bsv = Bs + s * BN * BKP;
        #pragma unroll
        for (int ks = 0; ks < BK; ks += 8) {
            wmma::fragment<wmma::matrix_a, 16, 16, 8, wmma::precision::tf32, wmma::row_major> fa[4];
            wmma::fragment<wmma::matrix_b, 16, 16, 8, wmma::precision::tf32, wmma::col_major> fb[2];
            #pragma unroll
            for (int i = 0; i < 4; i++) {
                wmma::load_matrix_sync(fa[i], Asv + (wm * 64 + i * 16) * BKP + ks, BKP);
                #pragma unroll
                for (int e = 0; e < fa[i].num_elements; e++)
                    fa[i].x[e] = wmma::__float_to_tf32(fa[i].x[e]);
            }
            #pragma unroll
            for (int j = 0; j < 2; j++) {
                wmma::load_matrix_sync(fb[j], Bsv + (wn * 32 + j * 16) * BKP + ks, BKP);
                #pragma unroll
                for (int e = 0; e < fb[j].num_elements; e++)
                    fb[j].x[e] = wmma::__float_to_tf32(fb[j].x[e]);
            }
            #pragma unroll
            for (int i = 0; i < 4; i++)
                #pragma unroll
                for (int j = 0; j < 2; j++)
                    wmma::mma_sync(acc[i][j], fa[i], fb[j], acc[i][j]);
        }
        __syncthreads();
    }

    // Stage C in smem (A/B buffers dead): Cs[BM][CNP]
    float* Cs = smem;
    #pragma unroll
    for (int i = 0; i < 4; i++)
        #pragma unroll
        for (int j = 0; j < 2; j++)
            wmma::store_matrix_sync(Cs + (wm * 64 + i * 16) * CNP + wn * 32 + j * 16,
                                    acc[i][j], CNP, wmma::mem_row_major);
    __syncthreads();

    // Epilogue: bias + rank-8 LoRA; 64 elements per thread
    #pragma unroll 4
    for (int e = tid; e < BM * BN; e += 256) {
        int r = e >> 7;           // BN=128
        int c = e & 127;
        int grow = row0 + r;
        int gcol = col0 + c;
        const float* tl  = TMP + grow * RR;
        const float* lbv = LB + (size_t)gcol * RR;
        float d8 = 0.f;
        #pragma unroll
        for (int q = 0; q < RR; q++) d8 += tl[q] * lbv[q];
        OUT[(size_t)grow * N + gcol] = Cs[r * CNP + c] + bias[gcol] + LORA_SCALE * d8;
    }
}

// ---------------------------------------------------------------------------
// Kernel 3: causal attention (flash-style, online softmax) — unchanged
// ---------------------------------------------------------------------------
__global__ __launch_bounds__(256)
void attn_kernel(const int* __restrict__ pad) {
    __shared__ float Ks[32][65];
    __shared__ float Vs[32][65];
    __shared__ float Qs[8][64];

    int warp = threadIdx.x >> 5;
    int lane = threadIdx.x & 31;
    int bh = blockIdx.y;
    int b = bh / HH, h = bh % HH;
    int q0 = blockIdx.x * 8;
    int qrow = q0 + warp;

    for (int e = threadIdx.x; e < 8*64; e += 256) {
        int r = e >> 6, d = e & 63;
        Qs[r][d] = g_qkv[(size_t)(b*TT + q0 + r) * NQKV + h*DD + d] * 0.125f;
    }

    float m = -INFINITY, ssum = 0.f, acc0 = 0.f, acc1 = 0.f;
    const int q_max_blk = q0 + 7;
    const int* padrow = pad + (size_t)b * TT * TT + (size_t)qrow * TT;

    int ldr  = threadIdx.x >> 3;
    int ldd  = (threadIdx.x & 7) * 8;

    for (int k0 = 0; k0 <= q_max_blk; k0 += 32) {
        __syncthreads();
        {
            const float* srck = g_qkv + (size_t)(b*TT + k0 + ldr) * NQKV + CC + h*DD + ldd;
            float4 a0 = *(const float4*)(srck);
            float4 a1 = *(const float4*)(srck + 4);
            const float* srcv = srck + CC;
            float4 b0 = *(const float4*)(srcv);
            float4 b1 = *(const float4*)(srcv + 4);
            Ks[ldr][ldd+0]=a0.x; Ks[ldr][ldd+1]=a0.y; Ks[ldr][ldd+2]=a0.z; Ks[ldr][ldd+3]=a0.w;
            Ks[ldr][ldd+4]=a1.x; Ks[ldr][ldd+5]=a1.y; Ks[ldr][ldd+6]=a1.z; Ks[ldr][ldd+7]=a1.w;
            Vs[ldr][ldd+0]=b0.x; Vs[ldr][ldd+1]=b0.y; Vs[ldr][ldd+2]=b0.z; Vs[ldr][ldd+3]=b0.w;
            Vs[ldr][ldd+4]=b1.x; Vs[ldr][ldd+5]=b1.y; Vs[ldr][ldd+6]=b1.z; Vs[ldr][ldd+7]=b1.w;
        }
        __syncthreads();

        if (k0 <= qrow) {
            int kt = k0 + lane;
            float dsum = 0.f;
            #pragma unroll 16
            for (int j = 0; j < 64; j++) dsum += Qs[warp][j] * Ks[lane][j];
            bool in_range = (kt <= qrow);
            bool pad_ok   = in_range && (padrow[kt] != 0);
            float score = pad_ok ? dsum : (in_range ? -3.0e38f : -INFINITY);

            float mx = score;
            #pragma unroll
            for (int o = 16; o > 0; o >>= 1) mx = fmaxf(mx, __shfl_xor_sync(0xffffffffu, mx, o));
            float mnew = fmaxf(m, mx);
            float corr = __expf(m - mnew);
            float p = __expf(score - mnew);

            float psum = p;
            #pragma unroll
            for (int o = 16; o > 0; o >>= 1) psum += __shfl_xor_sync(0xffffffffu, psum, o);
            ssum = ssum * corr + psum;
            acc0 *= corr; acc1 *= corr;
            #pragma unroll
            for (int j = 0; j < 32; j++) {
                float pj = __shfl_sync(0xffffffffu, p, j);
                acc0 += pj * Vs[j][lane];
                acc1 += pj * Vs[j][lane + 32];
            }
            m = mnew;
        }
    }

    float inv = 1.0f / ssum;
    size_t yoff = (size_t)(b*TT + qrow) * CC + h*DD;
    g_y[yoff + lane]      = acc0 * inv;
    g_y[yoff + lane + 32] = acc1 * inv;
}

// ---------------------------------------------------------------------------
extern "C" void kernel_launch(void* const* d_in, const int* in_sizes, int n_in,
                              void* d_out, int out_size) {
    const float* x       = (const float*)d_in[0];
    const int*   pad     = (const int*)  d_in[1];
    const float* attn_w  = (const float*)d_in[2];
    const float* attn_b  = (const float*)d_in[3];
    const float* la_attn = (const float*)d_in[4];
    const float* lb_attn = (const float*)d_in[5];
    const float* proj_w  = (const float*)d_in[6];
    const float* proj_b  = (const float*)d_in[7];
    const float* la_proj = (const float*)d_in[8];
    const float* lb_proj = (const float*)d_in[9];
    float* out = (float*)d_out;

    static int smem_set = 0;
    if (!smem_set) {
        cudaFuncSetAttribute(gemm_lora_tf32,
                             cudaFuncAttributeMaxDynamicSharedMemorySize, GEMM_SMEM);
        smem_set = 1;
    }

    lora_vec_kernel<<<MTOK, 256>>>(x, la_attn, 0);
    gemm_lora_tf32<<<dim3(NQKV/BN, MTOK/BM), 256, GEMM_SMEM>>>(x, attn_w, lb_attn, attn_b, nullptr, 0, NQKV);
    attn_kernel<<<dim3(TT/8, BB*HH), 256>>>(pad);
    lora_vec_kernel<<<MTOK, 256>>>(nullptr, la_proj, 1);
    gemm_lora_tf32<<<dim3(CC/BN, MTOK/BM), 256, GEMM_SMEM>>>(nullptr, proj_w, lb_proj, proj_b, out, 1, CC);
}

// round 5
// speedup vs baseline: 1.6822x; 1.3294x over previous
#include <cuda_runtime.h>
#include <mma.h>
#include <math.h>
#include <cstdint>

using namespace nvcuda;

// Problem constants
#define BB 4
#define TT 1024
#define CC 1024
#define HH 16
#define DD 64
#define RR 8
#define MTOK (BB*TT)        // 4096
#define NQKV (3*CC)         // 3072
#define LORA_SCALE 2.0f     // 16 / 8

// GEMM tiling
#define BM 128
#define BN 128
#define BK 32
#define BKP 36
#define CNP 132
#define NK (CC/BK)
#define GEMM_SMEM (2*(BM+BN)*BKP*4)   // 73728 bytes

// Scratch
__device__ float g_qkv[MTOK * NQKV];
__device__ float g_y[MTOK * CC];
__device__ float g_tmpa[MTOK * RR];
__device__ float g_tmpp[MTOK * RR];

__device__ __forceinline__ void cp_async16(void* sptr, const void* gptr) {
    unsigned int sa = (unsigned int)__cvta_generic_to_shared(sptr);
    asm volatile("cp.async.cg.shared.global [%0], [%1], 16;\n" :: "r"(sa), "l"(gptr));
}

// ---------------------------------------------------------------------------
// Kernel 1: rank-R LoRA vector
// ---------------------------------------------------------------------------
__global__ __launch_bounds__(256)
void lora_vec_kernel(const float* __restrict__ Xin, const float* __restrict__ LA, int mode) {
    const float* X  = (mode == 0) ? Xin : g_y;
    float* out      = (mode == 0) ? g_tmpa : g_tmpp;
    int row  = blockIdx.x;
    int warp = threadIdx.x >> 5;
    int lane = threadIdx.x & 31;
    const float* xr = X + (size_t)row * CC;
    const float* lr = LA + (size_t)warp * CC;
    float s = 0.f;
    #pragma unroll 8
    for (int k = lane; k < CC; k += 32) s += xr[k] * lr[k];
    #pragma unroll
    for (int o = 16; o > 0; o >>= 1) s += __shfl_xor_sync(0xffffffffu, s, o);
    if (lane == 0) out[row * RR + warp] = s;
}

// ---------------------------------------------------------------------------
// Kernel 2: tf32 GEMM (cp.async double-buffered) + LoRA + bias
// col_base: N-offset of this launch's tile grid (for split launches).
// ---------------------------------------------------------------------------
__global__ __launch_bounds__(256)
void gemm_lora_tf32(const float* __restrict__ Xin,
                    const float* __restrict__ W,
                    const float* __restrict__ LB,
                    const float* __restrict__ bias,
                    float* __restrict__ Oout,
                    int mode, int N, int col_base) {
    const int K = CC;
    const float* X   = (mode == 0) ? Xin : g_y;
    float*       OUT = (mode == 0) ? g_qkv : Oout;
    const float* TMP = (mode == 0) ? g_tmpa : g_tmpp;

    extern __shared__ float smem[];
    float* As = smem;
    float* Bs = smem + 2 * BM * BKP;

    int tid  = threadIdx.x;
    int warp = tid >> 5;
    int wm   = warp >> 2;
    int wn   = warp & 3;
    int row0 = blockIdx.y * BM;
    int col0 = col_base + blockIdx.x * BN;

    int lrow = tid >> 3;
    int lcol = (tid & 7) * 4;
    const float* Abase = X + (size_t)(row0 + lrow) * K + lcol;
    const float* Bbase = W + (size_t)(col0 + lrow) * K + lcol;

    wmma::fragment<wmma::accumulator, 16, 16, 8, float> acc[4][2];
    #pragma unroll
    for (int i = 0; i < 4; i++)
        #pragma unroll
        for (int j = 0; j < 2; j++) wmma::fill_fragment(acc[i][j], 0.0f);

    {
        float* Ad = As + lrow * BKP + lcol;
        float* Bd = Bs + lrow * BKP + lcol;
        #pragma unroll
        for (int j = 0; j < 4; j++) {
            cp_async16(Ad + j * 32 * BKP, Abase + (size_t)(32 * j) * K);
            cp_async16(Bd + j * 32 * BKP, Bbase + (size_t)(32 * j) * K);
        }
        asm volatile("cp.async.commit_group;\n");
    }

    for (int it = 0; it < NK; ++it) {
        if (it + 1 < NK) {
            int s = (it + 1) & 1;
            int k0 = (it + 1) * BK;
            float* Ad = As + s * BM * BKP + lrow * BKP + lcol;
            float* Bd = Bs + s * BN * BKP + lrow * BKP + lcol;
            #pragma unroll
            for (int j = 0; j < 4; j++) {
                cp_async16(Ad + j * 32 * BKP, Abase + (size_t)(32 * j) * K + k0);
                cp_async16(Bd + j * 32 * BKP, Bbase + (size_t)(32 * j) * K + k0);
            }
            asm volatile("cp.async.commit_group;\n");
            asm volatile("cp.async.wait_group 1;\n");
        } else {
            asm volatile("cp.async.wait_group 0;\n");
        }
        __syncthreads();

        int s = it & 1;
        const float* Asv = As + s * BM * BKP;
        const float* Bsv = Bs + s * BN * BKP;
        #pragma unroll
        for (int ks = 0; ks < BK; ks += 8) {
            wmma::fragment<wmma::matrix_a, 16, 16, 8, wmma::precision::tf32, wmma::row_major> fa[4];
            wmma::fragment<wmma::matrix_b, 16, 16, 8, wmma::precision::tf32, wmma::col_major> fb[2];
            #pragma unroll
            for (int i = 0; i < 4; i++) {
                wmma::load_matrix_sync(fa[i], Asv + (wm * 64 + i * 16) * BKP + ks, BKP);
                #pragma unroll
                for (int e = 0; e < fa[i].num_elements; e++)
                    fa[i].x[e] = wmma::__float_to_tf32(fa[i].x[e]);
            }
            #pragma unroll
            for (int j = 0; j < 2; j++) {
                wmma::load_matrix_sync(fb[j], Bsv + (wn * 32 + j * 16) * BKP + ks, BKP);
                #pragma unroll
                for (int e = 0; e < fb[j].num_elements; e++)
                    fb[j].x[e] = wmma::__float_to_tf32(fb[j].x[e]);
            }
            #pragma unroll
            for (int i = 0; i < 4; i++)
                #pragma unroll
                for (int j = 0; j < 2; j++)
                    wmma::mma_sync(acc[i][j], fa[i], fb[j], acc[i][j]);
        }
        __syncthreads();
    }

    float* Cs = smem;
    #pragma unroll
    for (int i = 0; i < 4; i++)
        #pragma unroll
        for (int j = 0; j < 2; j++)
            wmma::store_matrix_sync(Cs + (wm * 64 + i * 16) * CNP + wn * 32 + j * 16,
                                    acc[i][j], CNP, wmma::mem_row_major);
    __syncthreads();

    #pragma unroll 4
    for (int e = tid; e < BM * BN; e += 256) {
        int r = e >> 7;
        int c = e & 127;
        int grow = row0 + r;
        int gcol = col0 + c;
        const float* tl  = TMP + grow * RR;
        const float* lbv = LB + (size_t)gcol * RR;
        float d8 = 0.f;
        #pragma unroll
        for (int q = 0; q < RR; q++) d8 += tl[q] * lbv[q];
        OUT[(size_t)grow * N + gcol] = Cs[r * CNP + c] + bias[gcol] + LORA_SCALE * d8;
    }
}

// ---------------------------------------------------------------------------
// Kernel 3: causal attention v2 — 2 rows/warp, float4 LDS throughout.
// Block: 8 warps = 16 query rows. Grid (T/16, B*H).
// ---------------------------------------------------------------------------
__global__ __launch_bounds__(256)
void attn_kernel(const int* __restrict__ pad) {
    __shared__ float Ks[32][68];
    __shared__ float Vs[32][68];
    __shared__ float Qs[16][64];

    int tid  = threadIdx.x;
    int warp = tid >> 5;
    int lane = tid & 31;
    int bh = blockIdx.y;
    int b = bh / HH, h = bh % HH;
    int q0 = blockIdx.x * 16;
    int r0 = q0 + 2 * warp;
    int r1 = r0 + 1;

    // Load+scale 16 Q rows (16x64 floats = 256 float4, 1 per thread)
    {
        int qr = tid >> 4, qc = (tid & 15) * 4;
        float4 qv = *(const float4*)(g_qkv + (size_t)(b*TT + q0 + qr) * NQKV + h*DD + qc);
        qv.x *= 0.125f; qv.y *= 0.125f; qv.z *= 0.125f; qv.w *= 0.125f;
        *(float4*)&Qs[qr][qc] = qv;
    }

    float m0 = -INFINITY, m1 = -INFINITY, sum0 = 0.f, sum1 = 0.f;
    float acc[2][4] = {};
    const int* pr0 = pad + (size_t)b * TT * TT + (size_t)r0 * TT;
    const int* pr1 = pr0 + TT;

    int ldr = tid >> 3;             // 0..31 chunk key
    int ldd = (tid & 7) * 8;        // 0..56 dim
    int half = lane >> 4;           // 0/1 key parity in PV
    int qd = (lane & 15) * 4;       // PV dim group

    for (int k0 = 0; k0 <= q0 + 15; k0 += 32) {
        __syncthreads();
        {
            const float* srck = g_qkv + (size_t)(b*TT + k0 + ldr) * NQKV + CC + h*DD + ldd;
            float4 a0 = *(const float4*)(srck);
            float4 a1 = *(const float4*)(srck + 4);
            const float* srcv = srck + CC;
            float4 b0 = *(const float4*)(srcv);
            float4 b1 = *(const float4*)(srcv + 4);
            *(float4*)&Ks[ldr][ldd]     = a0;
            *(float4*)&Ks[ldr][ldd + 4] = a1;
            *(float4*)&Vs[ldr][ldd]     = b0;
            *(float4*)&Vs[ldr][ldd + 4] = b1;
        }
        __syncthreads();

        if (k0 <= r1) {
            int kt = k0 + lane;
            // dot products for both rows, lane = key
            float d0 = 0.f, d1 = 0.f;
            #pragma unroll
            for (int j = 0; j < 64; j += 4) {
                float4 kv = *(const float4*)&Ks[lane][j];
                float4 qa = *(const float4*)&Qs[2*warp][j];
                float4 qb = *(const float4*)&Qs[2*warp + 1][j];
                d0 += kv.x*qa.x + kv.y*qa.y + kv.z*qa.z + kv.w*qa.w;
                d1 += kv.x*qb.x + kv.y*qb.y + kv.z*qb.z + kv.w*qb.w;
            }
            bool ir0 = (kt <= r0), ir1 = (kt <= r1);
            float sc0 = ir0 ? ((pr0[kt] != 0) ? d0 : -3.0e38f) : -INFINITY;
            float sc1 = ir1 ? ((pr1[kt] != 0) ? d1 : -3.0e38f) : -INFINITY;

            float mx0 = sc0, mx1 = sc1;
            #pragma unroll
            for (int o = 16; o > 0; o >>= 1) {
                mx0 = fmaxf(mx0, __shfl_xor_sync(0xffffffffu, mx0, o));
                mx1 = fmaxf(mx1, __shfl_xor_sync(0xffffffffu, mx1, o));
            }
            float mn0 = fmaxf(m0, mx0), mn1 = fmaxf(m1, mx1);
            float c0 = __expf(m0 - mn0), c1 = __expf(m1 - mn1);
            float p0 = __expf(sc0 - mn0), p1 = __expf(sc1 - mn1);
            float ps0 = p0, ps1 = p1;
            #pragma unroll
            for (int o = 16; o > 0; o >>= 1) {
                ps0 += __shfl_xor_sync(0xffffffffu, ps0, o);
                ps1 += __shfl_xor_sync(0xffffffffu, ps1, o);
            }
            sum0 = sum0 * c0 + ps0;
            sum1 = sum1 * c1 + ps1;
            #pragma unroll
            for (int i = 0; i < 4; i++) { acc[0][i] *= c0; acc[1][i] *= c1; }
            m0 = mn0; m1 = mn1;

            // PV: half-warp per key, float4 V reads, 2 keys per iteration
            #pragma unroll
            for (int jj = 0; jj < 32; jj += 2) {
                int mj = jj + half;
                float pj0 = __shfl_sync(0xffffffffu, p0, mj);
                float pj1 = __shfl_sync(0xffffffffu, p1, mj);
                float4 v = *(const float4*)&Vs[mj][qd];
                acc[0][0] += pj0 * v.x; acc[0][1] += pj0 * v.y;
                acc[0][2] += pj0 * v.z; acc[0][3] += pj0 * v.w;
                acc[1][0] += pj1 * v.x; acc[1][1] += pj1 * v.y;
                acc[1][2] += pj1 * v.z; acc[1][3] += pj1 * v.w;
            }
        }
    }

    // Combine the two key-parity halves
    #pragma unroll
    for (int r = 0; r < 2; r++)
        #pragma unroll
        for (int i = 0; i < 4; i++)
            acc[r][i] += __shfl_xor_sync(0xffffffffu, acc[r][i], 16);

    // lanes 0-15 write row r0, lanes 16-31 write row r1
    int row  = half ? r1 : r0;
    float inv = 1.0f / (half ? sum1 : sum0);
    float4 o4;
    o4.x = acc[half][0] * inv; o4.y = acc[half][1] * inv;
    o4.z = acc[half][2] * inv; o4.w = acc[half][3] * inv;
    *(float4*)(g_y + (size_t)(b*TT + row) * CC + h*DD + qd) = o4;
}

// ---------------------------------------------------------------------------
extern "C" void kernel_launch(void* const* d_in, const int* in_sizes, int n_in,
                              void* d_out, int out_size) {
    const float* x       = (const float*)d_in[0];
    const int*   pad     = (const int*)  d_in[1];
    const float* attn_w  = (const float*)d_in[2];
    const float* attn_b  = (const float*)d_in[3];
    const float* la_attn = (const float*)d_in[4];
    const float* lb_attn = (const float*)d_in[5];
    const float* proj_w  = (const float*)d_in[6];
    const float* proj_b  = (const float*)d_in[7];
    const float* la_proj = (const float*)d_in[8];
    const float* lb_proj = (const float*)d_in[9];
    float* out = (float*)d_out;

    static int smem_set = 0;
    if (!smem_set) {
        cudaFuncSetAttribute(gemm_lora_tf32,
                             cudaFuncAttributeMaxDynamicSharedMemorySize, GEMM_SMEM);
        smem_set = 1;
    }

    // 6 launches/call so ncu -s 5 captures the proj GEMM (launch idx 5).
    lora_vec_kernel<<<MTOK, 256>>>(x, la_attn, 0);
    gemm_lora_tf32<<<dim3(NQKV/BN/2, MTOK/BM), 256, GEMM_SMEM>>>(x, attn_w, lb_attn, attn_b, nullptr, 0, NQKV, 0);
    gemm_lora_tf32<<<dim3(NQKV/BN/2, MTOK/BM), 256, GEMM_SMEM>>>(x, attn_w, lb_attn, attn_b, nullptr, 0, NQKV, NQKV/2);
    attn_kernel<<<dim3(TT/16, BB*HH), 256>>>(pad);
    lora_vec_kernel<<<MTOK, 256>>>(nullptr, la_proj, 1);
    gemm_lora_tf32<<<dim3(CC/BN, MTOK/BM), 256, GEMM_SMEM>>>(nullptr, proj_w, lb_proj, proj_b, out, 1, CC, 0);
}

// round 6
// speedup vs baseline: 2.7023x; 1.6064x over previous
#include <cuda_runtime.h>
#include <mma.h>
#include <math.h>
#include <cstdint>

using namespace nvcuda;

// Problem constants
#define BB 4
#define TT 1024
#define CC 1024
#define HH 16
#define DD 64
#define RR 8
#define MTOK (BB*TT)
#define NQKV (3*CC)
#define LORA_SCALE 2.0f

// GEMM tiling
#define BM 128
#define BN 128
#define BK 32
#define BKP 36
#define CNP 132
#define NK (CC/BK)
#define GEMM_SMEM (2*(BM+BN)*BKP*4)   // 73728 bytes

// Scratch
__device__ float g_qkv[MTOK * NQKV];
__device__ float g_y[MTOK * CC];
__device__ float g_tmpa[MTOK * RR];
__device__ float g_tmpp[MTOK * RR];
__device__ unsigned g_padbits[MTOK * 32];   // bit j of word w = pad[b][q][w*32+j]

__device__ __forceinline__ void cp_async16(void* sptr, const void* gptr) {
    unsigned int sa = (unsigned int)__cvta_generic_to_shared(sptr);
    asm volatile("cp.async.cg.shared.global [%0], [%1], 16;\n" :: "r"(sa), "l"(gptr));
}
__device__ __forceinline__ unsigned f2tf(float f) {
    unsigned u; asm("cvt.rna.tf32.f32 %0, %1;" : "=r"(u) : "f"(f)); return u;
}
// D += A(16x8) * B(8x8), tf32
__device__ __forceinline__ void mma8(float* d, const unsigned* a, unsigned b0, unsigned b1) {
    asm volatile(
        "mma.sync.aligned.m16n8k8.row.col.f32.tf32.tf32.f32 "
        "{%0,%1,%2,%3}, {%4,%5,%6,%7}, {%8,%9}, {%0,%1,%2,%3};\n"
        : "+f"(d[0]), "+f"(d[1]), "+f"(d[2]), "+f"(d[3])
        : "r"(a[0]), "r"(a[1]), "r"(a[2]), "r"(a[3]), "r"(b0), "r"(b1));
}

// ---------------------------------------------------------------------------
// Kernel 0: compress pad mask to bits. Block = one (b,q) row.
// ---------------------------------------------------------------------------
__global__ __launch_bounds__(256)
void padbits_kernel(const int* __restrict__ pad) {
    int row = blockIdx.x;                 // b*T + q
    int b = row >> 10;
    const int* base = pad + (size_t)b * TT * TT + (size_t)(row & 1023) * TT;
    int warp = threadIdx.x >> 5, lane = threadIdx.x & 31;
    #pragma unroll
    for (int i = 0; i < 4; i++) {
        int word = warp * 4 + i;
        unsigned bits = __ballot_sync(0xffffffffu, base[word * 32 + lane] != 0);
        if (lane == 0) g_padbits[row * 32 + word] = bits;
    }
}

// ---------------------------------------------------------------------------
// Kernel 1: rank-R LoRA vector
// ---------------------------------------------------------------------------
__global__ __launch_bounds__(256)
void lora_vec_kernel(const float* __restrict__ Xin, const float* __restrict__ LA, int mode) {
    const float* X  = (mode == 0) ? Xin : g_y;
    float* out      = (mode == 0) ? g_tmpa : g_tmpp;
    int row  = blockIdx.x;
    int warp = threadIdx.x >> 5;
    int lane = threadIdx.x & 31;
    const float* xr = X + (size_t)row * CC;
    const float* lr = LA + (size_t)warp * CC;
    float s = 0.f;
    #pragma unroll 8
    for (int k = lane; k < CC; k += 32) s += xr[k] * lr[k];
    #pragma unroll
    for (int o = 16; o > 0; o >>= 1) s += __shfl_xor_sync(0xffffffffu, s, o);
    if (lane == 0) out[row * RR + warp] = s;
}

// ---------------------------------------------------------------------------
// Kernel 2: tf32 GEMM (cp.async double-buffered) + LoRA + bias (unchanged)
// ---------------------------------------------------------------------------
__global__ __launch_bounds__(256)
void gemm_lora_tf32(const float* __restrict__ Xin,
                    const float* __restrict__ W,
                    const float* __restrict__ LB,
                    const float* __restrict__ bias,
                    float* __restrict__ Oout,
                    int mode, int N) {
    const int K = CC;
    const float* X   = (mode == 0) ? Xin : g_y;
    float*       OUT = (mode == 0) ? g_qkv : Oout;
    const float* TMP = (mode == 0) ? g_tmpa : g_tmpp;

    extern __shared__ float smem[];
    float* As = smem;
    float* Bs = smem + 2 * BM * BKP;

    int tid  = threadIdx.x;
    int warp = tid >> 5;
    int wm   = warp >> 2;
    int wn   = warp & 3;
    int row0 = blockIdx.y * BM;
    int col0 = blockIdx.x * BN;

    int lrow = tid >> 3;
    int lcol = (tid & 7) * 4;
    const float* Abase = X + (size_t)(row0 + lrow) * K + lcol;
    const float* Bbase = W + (size_t)(col0 + lrow) * K + lcol;

    wmma::fragment<wmma::accumulator, 16, 16, 8, float> acc[4][2];
    #pragma unroll
    for (int i = 0; i < 4; i++)
        #pragma unroll
        for (int j = 0; j < 2; j++) wmma::fill_fragment(acc[i][j], 0.0f);

    {
        float* Ad = As + lrow * BKP + lcol;
        float* Bd = Bs + lrow * BKP + lcol;
        #pragma unroll
        for (int j = 0; j < 4; j++) {
            cp_async16(Ad + j * 32 * BKP, Abase + (size_t)(32 * j) * K);
            cp_async16(Bd + j * 32 * BKP, Bbase + (size_t)(32 * j) * K);
        }
        asm volatile("cp.async.commit_group;\n");
    }

    for (int it = 0; it < NK; ++it) {
        if (it + 1 < NK) {
            int s = (it + 1) & 1;
            int k0 = (it + 1) * BK;
            float* Ad = As + s * BM * BKP + lrow * BKP + lcol;
            float* Bd = Bs + s * BN * BKP + lrow * BKP + lcol;
            #pragma unroll
            for (int j = 0; j < 4; j++) {
                cp_async16(Ad + j * 32 * BKP, Abase + (size_t)(32 * j) * K + k0);
                cp_async16(Bd + j * 32 * BKP, Bbase + (size_t)(32 * j) * K + k0);
            }
            asm volatile("cp.async.commit_group;\n");
            asm volatile("cp.async.wait_group 1;\n");
        } else {
            asm volatile("cp.async.wait_group 0;\n");
        }
        __syncthreads();

        int s = it & 1;
        const float* Asv = As + s * BM * BKP;
        const float* Bsv = Bs + s * BN * BKP;
        #pragma unroll
        for (int ks = 0; ks < BK; ks += 8) {
            wmma::fragment<wmma::matrix_a, 16, 16, 8, wmma::precision::tf32, wmma::row_major> fa[4];
            wmma::fragment<wmma::matrix_b, 16, 16, 8, wmma::precision::tf32, wmma::col_major> fb[2];
            #pragma unroll
            for (int i = 0; i < 4; i++) {
                wmma::load_matrix_sync(fa[i], Asv + (wm * 64 + i * 16) * BKP + ks, BKP);
                #pragma unroll
                for (int e = 0; e < fa[i].num_elements; e++)
                    fa[i].x[e] = wmma::__float_to_tf32(fa[i].x[e]);
            }
            #pragma unroll
            for (int j = 0; j < 2; j++) {
                wmma::load_matrix_sync(fb[j], Bsv + (wn * 32 + j * 16) * BKP + ks, BKP);
                #pragma unroll
                for (int e = 0; e < fb[j].num_elements; e++)
                    fb[j].x[e] = wmma::__float_to_tf32(fb[j].x[e]);
            }
            #pragma unroll
            for (int i = 0; i < 4; i++)
                #pragma unroll
                for (int j = 0; j < 2; j++)
                    wmma::mma_sync(acc[i][j], fa[i], fb[j], acc[i][j]);
        }
        __syncthreads();
    }

    float* Cs = smem;
    #pragma unroll
    for (int i = 0; i < 4; i++)
        #pragma unroll
        for (int j = 0; j < 2; j++)
            wmma::store_matrix_sync(Cs + (wm * 64 + i * 16) * CNP + wn * 32 + j * 16,
                                    acc[i][j], CNP, wmma::mem_row_major);
    __syncthreads();

    #pragma unroll 4
    for (int e = tid; e < BM * BN; e += 256) {
        int r = e >> 7;
        int c = e & 127;
        int grow = row0 + r;
        int gcol = col0 + c;
        const float* tl  = TMP + grow * RR;
        const float* lbv = LB + (size_t)gcol * RR;
        float d8 = 0.f;
        #pragma unroll
        for (int q = 0; q < RR; q++) d8 += tl[q] * lbv[q];
        OUT[(size_t)grow * N + gcol] = Cs[r * CNP + c] + bias[gcol] + LORA_SCALE * d8;
    }
}

// ---------------------------------------------------------------------------
// Kernel 3: attention v3 — tensor-core FA2 (mma.m16n8k8 tf32).
// Block: 8 warps x 16 q-rows = 128 rows of one (b,h). 32-key chunks,
// cp.async double-buffered. Grid (8, B*H), big tiles scheduled first.
// ---------------------------------------------------------------------------
__global__ __launch_bounds__(256, 2)
void attn_mma_kernel() {
    __shared__ float Ks[2][32][68];
    __shared__ float Vs[2][32][72];

    int tid  = threadIdx.x;
    int warp = tid >> 5;
    int lane = tid & 31;
    int g = lane >> 2;          // quad row 0..7
    int m = lane & 3;           // quad col 0..3
    int bh = blockIdx.y;
    int b = bh / HH, h = bh % HH;
    int qt = 7 - blockIdx.x;    // big tiles first
    int q0 = qt * 128;
    int qr_lo = q0 + warp * 16 + g;
    int qr_hi = qr_lo + 8;

    // Q fragments: 8 k-steps x {(g,m),(g+8,m),(g,m+4),(g+8,m+4)}, tf32, scaled
    unsigned qf[8][4];
    {
        const float* qlo = g_qkv + (size_t)(b*TT + qr_lo) * NQKV + h*DD;
        const float* qhi = qlo + (size_t)8 * NQKV;
        #pragma unroll
        for (int ks = 0; ks < 8; ks++) {
            qf[ks][0] = f2tf(qlo[ks*8 + m]     * 0.125f);
            qf[ks][1] = f2tf(qhi[ks*8 + m]     * 0.125f);
            qf[ks][2] = f2tf(qlo[ks*8 + m + 4] * 0.125f);
            qf[ks][3] = f2tf(qhi[ks*8 + m + 4] * 0.125f);
        }
    }

    float o[8][4];
    #pragma unroll
    for (int i = 0; i < 8; i++) { o[i][0]=0.f; o[i][1]=0.f; o[i][2]=0.f; o[i][3]=0.f; }
    float m_lo = -INFINITY, m_hi = -INFINITY, s_lo = 0.f, s_hi = 0.f;

    // Staging map: thread t handles K float4 ids {2t,2t+1}, same for V.
    int strow = tid >> 3;              // 0..31
    int stc   = (tid & 7) * 8;         // float offset (two float4)
    const float* kgbase = g_qkv + (size_t)(b*TT) * NQKV + CC  + h*DD;
    const float* vgbase = g_qkv + (size_t)(b*TT) * NQKV + 2*CC + h*DD;

    int nchunks = q0/32 + 4;
    int warp_last = q0 + warp*16 + 15;   // last q-row this warp owns

    // Prologue: stage chunk 0
    {
        const float* ks_ = kgbase + (size_t)strow * NQKV + stc;
        const float* vs_ = vgbase + (size_t)strow * NQKV + stc;
        cp_async16(&Ks[0][strow][stc],     ks_);
        cp_async16(&Ks[0][strow][stc + 4], ks_ + 4);
        cp_async16(&Vs[0][strow][stc],     vs_);
        cp_async16(&Vs[0][strow][stc + 4], vs_ + 4);
        asm volatile("cp.async.commit_group;\n");
    }

    int src1 = (lane & ~3) | (m >> 1);
    int src2 = src1 + 2;
    bool odd = (m & 1);

    for (int ic = 0; ic < nchunks; ic++) {
        if (ic + 1 < nchunks) {
            int s = (ic + 1) & 1;
            int tok = (ic + 1) * 32 + strow;
            const float* ks_ = kgbase + (size_t)tok * NQKV + stc;
            const float* vs_ = vgbase + (size_t)tok * NQKV + stc;
            cp_async16(&Ks[s][strow][stc],     ks_);
            cp_async16(&Ks[s][strow][stc + 4], ks_ + 4);
            cp_async16(&Vs[s][strow][stc],     vs_);
            cp_async16(&Vs[s][strow][stc + 4], vs_ + 4);
            asm volatile("cp.async.commit_group;\n");
            asm volatile("cp.async.wait_group 1;\n");
        } else {
            asm volatile("cp.async.wait_group 0;\n");
        }
        __syncthreads();

        int k0 = ic * 32;
        if (k0 <= warp_last) {
            int s = ic & 1;
            // ---- S = Q K^T : 4 n-tiles (8 keys each) ----
            float sc[4][4];
            #pragma unroll
            for (int nt = 0; nt < 4; nt++) { sc[nt][0]=0.f; sc[nt][1]=0.f; sc[nt][2]=0.f; sc[nt][3]=0.f; }
            #pragma unroll
            for (int ks = 0; ks < 8; ks++) {
                #pragma unroll
                for (int nt = 0; nt < 4; nt++) {
                    unsigned b0 = __float_as_uint(Ks[s][nt*8 + g][ks*8 + m]);
                    unsigned b1 = __float_as_uint(Ks[s][nt*8 + g][ks*8 + m + 4]);
                    mma8(sc[nt], qf[ks], b0, b1);
                }
            }
            // ---- mask ----
            unsigned pw_lo = g_padbits[(size_t)(b*TT + qr_lo)*32 + ic];
            unsigned pw_hi = g_padbits[(size_t)(b*TT + qr_hi)*32 + ic];
            #pragma unroll
            for (int nt = 0; nt < 4; nt++) {
                int bitA = nt*8 + 2*m, bitB = bitA + 1;
                int kA = k0 + bitA, kB = k0 + bitB;
                if (!(kA <= qr_lo && ((pw_lo >> bitA) & 1))) sc[nt][0] = -3.0e38f;
                if (!(kB <= qr_lo && ((pw_lo >> bitB) & 1))) sc[nt][1] = -3.0e38f;
                if (!(kA <= qr_hi && ((pw_hi >> bitA) & 1))) sc[nt][2] = -3.0e38f;
                if (!(kB <= qr_hi && ((pw_hi >> bitB) & 1))) sc[nt][3] = -3.0e38f;
            }
            // ---- online softmax ----
            float mx_lo = sc[0][0], mx_hi = sc[0][2];
            #pragma unroll
            for (int nt = 0; nt < 4; nt++) {
                mx_lo = fmaxf(mx_lo, fmaxf(sc[nt][0], sc[nt][1]));
                mx_hi = fmaxf(mx_hi, fmaxf(sc[nt][2], sc[nt][3]));
            }
            mx_lo = fmaxf(mx_lo, __shfl_xor_sync(0xffffffffu, mx_lo, 1));
            mx_lo = fmaxf(mx_lo, __shfl_xor_sync(0xffffffffu, mx_lo, 2));
            mx_hi = fmaxf(mx_hi, __shfl_xor_sync(0xffffffffu, mx_hi, 1));
            mx_hi = fmaxf(mx_hi, __shfl_xor_sync(0xffffffffu, mx_hi, 2));
            float mn_lo = fmaxf(m_lo, mx_lo), mn_hi = fmaxf(m_hi, mx_hi);
            float c_lo = __expf(m_lo - mn_lo), c_hi = __expf(m_hi - mn_hi);
            float ps_lo = 0.f, ps_hi = 0.f;
            #pragma unroll
            for (int nt = 0; nt < 4; nt++) {
                sc[nt][0] = __expf(sc[nt][0] - mn_lo);
                sc[nt][1] = __expf(sc[nt][1] - mn_lo);
                sc[nt][2] = __expf(sc[nt][2] - mn_hi);
                sc[nt][3] = __expf(sc[nt][3] - mn_hi);
                ps_lo += sc[nt][0] + sc[nt][1];
                ps_hi += sc[nt][2] + sc[nt][3];
            }
            ps_lo += __shfl_xor_sync(0xffffffffu, ps_lo, 1);
            ps_lo += __shfl_xor_sync(0xffffffffu, ps_lo, 2);
            ps_hi += __shfl_xor_sync(0xffffffffu, ps_hi, 1);
            ps_hi += __shfl_xor_sync(0xffffffffu, ps_hi, 2);
            s_lo = s_lo * c_lo + ps_lo;
            s_hi = s_hi * c_hi + ps_hi;
            #pragma unroll
            for (int nv = 0; nv < 8; nv++) {
                o[nv][0] *= c_lo; o[nv][1] *= c_lo;
                o[nv][2] *= c_hi; o[nv][3] *= c_hi;
            }
            m_lo = mn_lo; m_hi = mn_hi;
            // ---- O += P V : repack P accum->A frag, then 8 dim-tiles ----
            #pragma unroll
            for (int kp = 0; kp < 4; kp++) {
                float v0 = __shfl_sync(0xffffffffu, sc[kp][0], src1);
                float v1 = __shfl_sync(0xffffffffu, sc[kp][1], src1);
                float v2 = __shfl_sync(0xffffffffu, sc[kp][0], src2);
                float v3 = __shfl_sync(0xffffffffu, sc[kp][1], src2);
                float w0 = __shfl_sync(0xffffffffu, sc[kp][2], src1);
                float w1 = __shfl_sync(0xffffffffu, sc[kp][3], src1);
                float w2 = __shfl_sync(0xffffffffu, sc[kp][2], src2);
                float w3 = __shfl_sync(0xffffffffu, sc[kp][3], src2);
                unsigned pa[4];
                pa[0] = f2tf(odd ? v1 : v0);
                pa[1] = f2tf(odd ? w1 : w0);
                pa[2] = f2tf(odd ? v3 : v2);
                pa[3] = f2tf(odd ? w3 : w2);
                #pragma unroll
                for (int nv = 0; nv < 8; nv++) {
                    unsigned b0 = __float_as_uint(Vs[s][kp*8 + m][nv*8 + g]);
                    unsigned b1 = __float_as_uint(Vs[s][kp*8 + m + 4][nv*8 + g]);
                    mma8(o[nv], pa, b0, b1);
                }
            }
        }
        __syncthreads();
    }

    // Epilogue
    float il = 1.0f / s_lo, ih = 1.0f / s_hi;
    float* ylo = g_y + (size_t)(b*TT + qr_lo) * CC + h*DD;
    float* yhi = g_y + (size_t)(b*TT + qr_hi) * CC + h*DD;
    #pragma unroll
    for (int nv = 0; nv < 8; nv++) {
        float2 a = make_float2(o[nv][0] * il, o[nv][1] * il);
        float2 c = make_float2(o[nv][2] * ih, o[nv][3] * ih);
        *(float2*)&ylo[nv*8 + 2*m] = a;
        *(float2*)&yhi[nv*8 + 2*m] = c;
    }
}

// ---------------------------------------------------------------------------
extern "C" void kernel_launch(void* const* d_in, const int* in_sizes, int n_in,
                              void* d_out, int out_size) {
    const float* x       = (const float*)d_in[0];
    const int*   pad     = (const int*)  d_in[1];
    const float* attn_w  = (const float*)d_in[2];
    const float* attn_b  = (const float*)d_in[3];
    const float* la_attn = (const float*)d_in[4];
    const float* lb_attn = (const float*)d_in[5];
    const float* proj_w  = (const float*)d_in[6];
    const float* proj_b  = (const float*)d_in[7];
    const float* la_proj = (const float*)d_in[8];
    const float* lb_proj = (const float*)d_in[9];
    float* out = (float*)d_out;

    static int smem_set = 0;
    if (!smem_set) {
        cudaFuncSetAttribute(gemm_lora_tf32,
                             cudaFuncAttributeMaxDynamicSharedMemorySize, GEMM_SMEM);
        smem_set = 1;
    }

    padbits_kernel<<<MTOK, 256>>>(pad);
    lora_vec_kernel<<<MTOK, 256>>>(x, la_attn, 0);
    gemm_lora_tf32<<<dim3(NQKV/BN, MTOK/BM), 256, GEMM_SMEM>>>(x, attn_w, lb_attn, attn_b, nullptr, 0, NQKV);
    attn_mma_kernel<<<dim3(8, BB*HH), 256>>>();
    lora_vec_kernel<<<MTOK, 256>>>(nullptr, la_proj, 1);
    gemm_lora_tf32<<<dim3(CC/BN, MTOK/BM), 256, GEMM_SMEM>>>(nullptr, proj_w, lb_proj, proj_b, out, 1, CC);
}

// round 11
// speedup vs baseline: 2.9911x; 1.1069x over previous
#include <cuda_runtime.h>
#include <mma.h>
#include <math.h>
#include <cstdint>

using namespace nvcuda;

// Problem constants
#define BB 4
#define TT 1024
#define CC 1024
#define HH 16
#define DD 64
#define RR 8
#define MTOK (BB*TT)
#define NQKV (3*CC)
#define LORA_SCALE 2.0f

// GEMM tiling
#define BM 128
#define BN 128
#define BK 32
#define BKP 36
#define CNP 132
#define NK (CC/BK)
#define GEMM_SMEM (2*(BM+BN)*BKP*4)   // 73728 bytes

// Scratch — identical set to round 6 (the last passing config)
__device__ float g_qkv[MTOK * NQKV];   // 48 MiB
__device__ float g_y[MTOK * CC];       // 16 MiB: x_tf32 before attn, y after
__device__ float g_tmpa[MTOK * RR];
__device__ float g_tmpp[MTOK * RR];
__device__ unsigned g_padbits[MTOK * 32];

__device__ __forceinline__ void cp_async16(void* sptr, const void* gptr) {
    unsigned int sa = (unsigned int)__cvta_generic_to_shared(sptr);
    asm volatile("cp.async.cg.shared.global [%0], [%1], 16;\n" :: "r"(sa), "l"(gptr));
}
__device__ __forceinline__ unsigned f2tf(float f) {
    unsigned u; asm("cvt.rna.tf32.f32 %0, %1;" : "=r"(u) : "f"(f)); return u;
}
__device__ __forceinline__ float f2tff(float f) {
    return __uint_as_float(f2tf(f));
}
__device__ __forceinline__ void mma8(float* d, const unsigned* a, unsigned b0, unsigned b1) {
    asm volatile(
        "mma.sync.aligned.m16n8k8.row.col.f32.tf32.tf32.f32 "
        "{%0,%1,%2,%3}, {%4,%5,%6,%7}, {%8,%9}, {%0,%1,%2,%3};\n"
        : "+f"(d[0]), "+f"(d[1]), "+f"(d[2]), "+f"(d[3])
        : "r"(a[0]), "r"(a[1]), "r"(a[2]), "r"(a[3]), "r"(b0), "r"(b1));
}

// ---------------------------------------------------------------------------
// Kernel 0: compress pad mask to bits AND stage tf32-rounded x into g_y.
// One block per (b,q) row: 8 warps ballot 32 pad words; each thread also
// rounds one float4 of x[row] into g_y[row].
// ---------------------------------------------------------------------------
__global__ __launch_bounds__(256)
void padbits_kernel(const int* __restrict__ pad, const float* __restrict__ x) {
    int row = blockIdx.x;
    int b = row >> 10;
    const int* base = pad + (size_t)b * TT * TT + (size_t)(row & 1023) * TT;
    int warp = threadIdx.x >> 5, lane = threadIdx.x & 31;
    #pragma unroll
    for (int i = 0; i < 4; i++) {
        int word = warp * 4 + i;
        unsigned bits = __ballot_sync(0xffffffffu, base[word * 32 + lane] != 0);
        if (lane == 0) g_padbits[row * 32 + word] = bits;
    }
    // x row -> tf32-rounded g_y row (1024 floats = 256 float4, 1 per thread)
    int c = threadIdx.x * 4;
    float4 v = *(const float4*)(x + (size_t)row * CC + c);
    v.x = f2tff(v.x); v.y = f2tff(v.y); v.z = f2tff(v.z); v.w = f2tff(v.w);
    *(float4*)(g_y + (size_t)row * CC + c) = v;
}

// ---------------------------------------------------------------------------
// Kernel 1: rank-R LoRA vector (identical to round 6)
// ---------------------------------------------------------------------------
__global__ __launch_bounds__(256)
void lora_vec_kernel(const float* __restrict__ Xin, const float* __restrict__ LA, int mode) {
    const float* X  = (mode == 0) ? Xin : g_y;
    float* out      = (mode == 0) ? g_tmpa : g_tmpp;
    int row  = blockIdx.x;
    int warp = threadIdx.x >> 5;
    int lane = threadIdx.x & 31;
    const float* xr = X + (size_t)row * CC;
    const float* lr = LA + (size_t)warp * CC;
    float s = 0.f;
    #pragma unroll 8
    for (int k = lane; k < CC; k += 32) s += xr[k] * lr[k];
    #pragma unroll
    for (int o = 16; o > 0; o >>= 1) s += __shfl_xor_sync(0xffffffffu, s, o);
    if (lane == 0) out[row * RR + warp] = s;
}

// ---------------------------------------------------------------------------
// Kernel 2: tf32 GEMM + LoRA + bias, template<MODE> (compile-time only).
// MODE 0 (QKV): A = g_y holding pre-rounded x -> NO fa cvts.
// MODE 1 (proj): A = g_y holding y -> fa cvts; byte-identical math to round 6.
// B = raw weights, fb cvts in both modes.
// ---------------------------------------------------------------------------
template<int MODE>
__global__ __launch_bounds__(256)
void gemm_lora_tf32(const float* __restrict__ Wraw,
                    const float* __restrict__ LB,
                    const float* __restrict__ bias,
                    float* __restrict__ Oout) {
    const int K = CC;
    const int N = (MODE == 0) ? NQKV : CC;
    float*       OUT = (MODE == 0) ? g_qkv : Oout;
    const float* TMP = (MODE == 0) ? g_tmpa : g_tmpp;

    extern __shared__ float smem[];
    float* As = smem;
    float* Bs = smem + 2 * BM * BKP;

    int tid  = threadIdx.x;
    int warp = tid >> 5;
    int wm   = warp >> 2;
    int wn   = warp & 3;
    int row0 = blockIdx.y * BM;
    int col0 = blockIdx.x * BN;

    int lrow = tid >> 3;
    int lcol = (tid & 7) * 4;
    const float* Abase = g_y  + (size_t)(row0 + lrow) * K + lcol;
    const float* Bbase = Wraw + (size_t)(col0 + lrow) * K + lcol;

    wmma::fragment<wmma::accumulator, 16, 16, 8, float> acc[4][2];
    #pragma unroll
    for (int i = 0; i < 4; i++)
        #pragma unroll
        for (int j = 0; j < 2; j++) wmma::fill_fragment(acc[i][j], 0.0f);

    {
        float* Ad = As + lrow * BKP + lcol;
        float* Bd = Bs + lrow * BKP + lcol;
        #pragma unroll
        for (int j = 0; j < 4; j++) {
            cp_async16(Ad + j * 32 * BKP, Abase + (size_t)(32 * j) * K);
            cp_async16(Bd + j * 32 * BKP, Bbase + (size_t)(32 * j) * K);
        }
        asm volatile("cp.async.commit_group;\n");
    }

    for (int it = 0; it < NK; ++it) {
        if (it + 1 < NK) {
            int s = (it + 1) & 1;
            int k0 = (it + 1) * BK;
            float* Ad = As + s * BM * BKP + lrow * BKP + lcol;
            float* Bd = Bs + s * BN * BKP + lrow * BKP + lcol;
            #pragma unroll
            for (int j = 0; j < 4; j++) {
                cp_async16(Ad + j * 32 * BKP, Abase + (size_t)(32 * j) * K + k0);
                cp_async16(Bd + j * 32 * BKP, Bbase + (size_t)(32 * j) * K + k0);
            }
            asm volatile("cp.async.commit_group;\n");
            asm volatile("cp.async.wait_group 1;\n");
        } else {
            asm volatile("cp.async.wait_group 0;\n");
        }
        __syncthreads();

        int s = it & 1;
        const float* Asv = As + s * BM * BKP;
        const float* Bsv = Bs + s * BN * BKP;
        #pragma unroll
        for (int ks = 0; ks < BK; ks += 8) {
            wmma::fragment<wmma::matrix_a, 16, 16, 8, wmma::precision::tf32, wmma::row_major> fa[4];
            wmma::fragment<wmma::matrix_b, 16, 16, 8, wmma::precision::tf32, wmma::col_major> fb[2];
            #pragma unroll
            for (int i = 0; i < 4; i++) {
                wmma::load_matrix_sync(fa[i], Asv + (wm * 64 + i * 16) * BKP + ks, BKP);
                if (MODE == 1) {
                    #pragma unroll
                    for (int e = 0; e < fa[i].num_elements; e++)
                        fa[i].x[e] = wmma::__float_to_tf32(fa[i].x[e]);
                }
            }
            #pragma unroll
            for (int j = 0; j < 2; j++) {
                wmma::load_matrix_sync(fb[j], Bsv + (wn * 32 + j * 16) * BKP + ks, BKP);
                #pragma unroll
                for (int e = 0; e < fb[j].num_elements; e++)
                    fb[j].x[e] = wmma::__float_to_tf32(fb[j].x[e]);
            }
            #pragma unroll
            for (int i = 0; i < 4; i++)
                #pragma unroll
                for (int j = 0; j < 2; j++)
                    wmma::mma_sync(acc[i][j], fa[i], fb[j], acc[i][j]);
        }
        __syncthreads();
    }

    float* Cs = smem;
    #pragma unroll
    for (int i = 0; i < 4; i++)
        #pragma unroll
        for (int j = 0; j < 2; j++)
            wmma::store_matrix_sync(Cs + (wm * 64 + i * 16) * CNP + wn * 32 + j * 16,
                                    acc[i][j], CNP, wmma::mem_row_major);
    __syncthreads();

    #pragma unroll 4
    for (int e = tid; e < BM * BN; e += 256) {
        int r = e >> 7;
        int c = e & 127;
        int grow = row0 + r;
        int gcol = col0 + c;
        const float* tl  = TMP + grow * RR;
        const float* lbv = LB + (size_t)gcol * RR;
        float d8 = 0.f;
        #pragma unroll
        for (int q = 0; q < RR; q++) d8 += tl[q] * lbv[q];
        OUT[(size_t)grow * N + gcol] = Cs[r * CNP + c] + bias[gcol] + LORA_SCALE * d8;
    }
}

// ---------------------------------------------------------------------------
// Kernel 3: attention — tensor-core FA2, BYTE-IDENTICAL to round 6.
// ---------------------------------------------------------------------------
__global__ __launch_bounds__(256, 2)
void attn_mma_kernel() {
    __shared__ float Ks[2][32][68];
    __shared__ float Vs[2][32][72];

    int tid  = threadIdx.x;
    int warp = tid >> 5;
    int lane = tid & 31;
    int g = lane >> 2;
    int m = lane & 3;
    int bh = blockIdx.y;
    int b = bh / HH, h = bh % HH;
    int qt = 7 - blockIdx.x;
    int q0 = qt * 128;
    int qr_lo = q0 + warp * 16 + g;
    int qr_hi = qr_lo + 8;

    unsigned qf[8][4];
    {
        const float* qlo = g_qkv + (size_t)(b*TT + qr_lo) * NQKV + h*DD;
        const float* qhi = qlo + (size_t)8 * NQKV;
        #pragma unroll
        for (int ks = 0; ks < 8; ks++) {
            qf[ks][0] = f2tf(qlo[ks*8 + m]     * 0.125f);
            qf[ks][1] = f2tf(qhi[ks*8 + m]     * 0.125f);
            qf[ks][2] = f2tf(qlo[ks*8 + m + 4] * 0.125f);
            qf[ks][3] = f2tf(qhi[ks*8 + m + 4] * 0.125f);
        }
    }

    float o[8][4];
    #pragma unroll
    for (int i = 0; i < 8; i++) { o[i][0]=0.f; o[i][1]=0.f; o[i][2]=0.f; o[i][3]=0.f; }
    float m_lo = -INFINITY, m_hi = -INFINITY, s_lo = 0.f, s_hi = 0.f;

    int strow = tid >> 3;
    int stc   = (tid & 7) * 8;
    const float* kgbase = g_qkv + (size_t)(b*TT) * NQKV + CC  + h*DD;
    const float* vgbase = g_qkv + (size_t)(b*TT) * NQKV + 2*CC + h*DD;

    int nchunks = q0/32 + 4;
    int warp_last = q0 + warp*16 + 15;

    {
        const float* ks_ = kgbase + (size_t)strow * NQKV + stc;
        const float* vs_ = vgbase + (size_t)strow * NQKV + stc;
        cp_async16(&Ks[0][strow][stc],     ks_);
        cp_async16(&Ks[0][strow][stc + 4], ks_ + 4);
        cp_async16(&Vs[0][strow][stc],     vs_);
        cp_async16(&Vs[0][strow][stc + 4], vs_ + 4);
        asm volatile("cp.async.commit_group;\n");
    }

    int src1 = (lane & ~3) | (m >> 1);
    int src2 = src1 + 2;
    bool odd = (m & 1);

    for (int ic = 0; ic < nchunks; ic++) {
        if (ic + 1 < nchunks) {
            int s = (ic + 1) & 1;
            int tok = (ic + 1) * 32 + strow;
            const float* ks_ = kgbase + (size_t)tok * NQKV + stc;
            const float* vs_ = vgbase + (size_t)tok * NQKV + stc;
            cp_async16(&Ks[s][strow][stc],     ks_);
            cp_async16(&Ks[s][strow][stc + 4], ks_ + 4);
            cp_async16(&Vs[s][strow][stc],     vs_);
            cp_async16(&Vs[s][strow][stc + 4], vs_ + 4);
            asm volatile("cp.async.commit_group;\n");
            asm volatile("cp.async.wait_group 1;\n");
        } else {
            asm volatile("cp.async.wait_group 0;\n");
        }
        __syncthreads();

        int k0 = ic * 32;
        if (k0 <= warp_last) {
            int s = ic & 1;
            float sc[4][4];
            #pragma unroll
            for (int nt = 0; nt < 4; nt++) { sc[nt][0]=0.f; sc[nt][1]=0.f; sc[nt][2]=0.f; sc[nt][3]=0.f; }
            #pragma unroll
            for (int ks = 0; ks < 8; ks++) {
                #pragma unroll
                for (int nt = 0; nt < 4; nt++) {
                    unsigned b0 = __float_as_uint(Ks[s][nt*8 + g][ks*8 + m]);
                    unsigned b1 = __float_as_uint(Ks[s][nt*8 + g][ks*8 + m + 4]);
                    mma8(sc[nt], qf[ks], b0, b1);
                }
            }
            unsigned pw_lo = g_padbits[(size_t)(b*TT + qr_lo)*32 + ic];
            unsigned pw_hi = g_padbits[(size_t)(b*TT + qr_hi)*32 + ic];
            #pragma unroll
            for (int nt = 0; nt < 4; nt++) {
                int bitA = nt*8 + 2*m, bitB = bitA + 1;
                int kA = k0 + bitA, kB = k0 + bitB;
                if (!(kA <= qr_lo && ((pw_lo >> bitA) & 1))) sc[nt][0] = -3.0e38f;
                if (!(kB <= qr_lo && ((pw_lo >> bitB) & 1))) sc[nt][1] = -3.0e38f;
                if (!(kA <= qr_hi && ((pw_hi >> bitA) & 1))) sc[nt][2] = -3.0e38f;
                if (!(kB <= qr_hi && ((pw_hi >> bitB) & 1))) sc[nt][3] = -3.0e38f;
            }
            float mx_lo = sc[0][0], mx_hi = sc[0][2];
            #pragma unroll
            for (int nt = 0; nt < 4; nt++) {
                mx_lo = fmaxf(mx_lo, fmaxf(sc[nt][0], sc[nt][1]));
                mx_hi = fmaxf(mx_hi, fmaxf(sc[nt][2], sc[nt][3]));
            }
            mx_lo = fmaxf(mx_lo, __shfl_xor_sync(0xffffffffu, mx_lo, 1));
            mx_lo = fmaxf(mx_lo, __shfl_xor_sync(0xffffffffu, mx_lo, 2));
            mx_hi = fmaxf(mx_hi, __shfl_xor_sync(0xffffffffu, mx_hi, 1));
            mx_hi = fmaxf(mx_hi, __shfl_xor_sync(0xffffffffu, mx_hi, 2));
            float mn_lo = fmaxf(m_lo, mx_lo), mn_hi = fmaxf(m_hi, mx_hi);
            float c_lo = __expf(m_lo - mn_lo), c_hi = __expf(m_hi - mn_hi);
            float ps_lo = 0.f, ps_hi = 0.f;
            #pragma unroll
            for (int nt = 0; nt < 4; nt++) {
                sc[nt][0] = __expf(sc[nt][0] - mn_lo);
                sc[nt][1] = __expf(sc[nt][1] - mn_lo);
                sc[nt][2] = __expf(sc[nt][2] - mn_hi);
                sc[nt][3] = __expf(sc[nt][3] - mn_hi);
                ps_lo += sc[nt][0] + sc[nt][1];
                ps_hi += sc[nt][2] + sc[nt][3];
            }
            ps_lo += __shfl_xor_sync(0xffffffffu, ps_lo, 1);
            ps_lo += __shfl_xor_sync(0xffffffffu, ps_lo, 2);
            ps_hi += __shfl_xor_sync(0xffffffffu, ps_hi, 1);
            ps_hi += __shfl_xor_sync(0xffffffffu, ps_hi, 2);
            s_lo = s_lo * c_lo + ps_lo;
            s_hi = s_hi * c_hi + ps_hi;
            #pragma unroll
            for (int nv = 0; nv < 8; nv++) {
                o[nv][0] *= c_lo; o[nv][1] *= c_lo;
                o[nv][2] *= c_hi; o[nv][3] *= c_hi;
            }
            m_lo = mn_lo; m_hi = mn_hi;
            #pragma unroll
            for (int kp = 0; kp < 4; kp++) {
                float v0 = __shfl_sync(0xffffffffu, sc[kp][0], src1);
                float v1 = __shfl_sync(0xffffffffu, sc[kp][1], src1);
                float v2 = __shfl_sync(0xffffffffu, sc[kp][0], src2);
                float v3 = __shfl_sync(0xffffffffu, sc[kp][1], src2);
                float w0 = __shfl_sync(0xffffffffu, sc[kp][2], src1);
                float w1 = __shfl_sync(0xffffffffu, sc[kp][3], src1);
                float w2 = __shfl_sync(0xffffffffu, sc[kp][2], src2);
                float w3 = __shfl_sync(0xffffffffu, sc[kp][3], src2);
                unsigned pa[4];
                pa[0] = f2tf(odd ? v1 : v0);
                pa[1] = f2tf(odd ? w1 : w0);
                pa[2] = f2tf(odd ? v3 : v2);
                pa[3] = f2tf(odd ? w3 : w2);
                #pragma unroll
                for (int nv = 0; nv < 8; nv++) {
                    unsigned b0 = __float_as_uint(Vs[s][kp*8 + m][nv*8 + g]);
                    unsigned b1 = __float_as_uint(Vs[s][kp*8 + m + 4][nv*8 + g]);
                    mma8(o[nv], pa, b0, b1);
                }
            }
        }
        __syncthreads();
    }

    float il = 1.0f / s_lo, ih = 1.0f / s_hi;
    float* ylo = g_y + (size_t)(b*TT + qr_lo) * CC + h*DD;
    float* yhi = g_y + (size_t)(b*TT + qr_hi) * CC + h*DD;
    #pragma unroll
    for (int nv = 0; nv < 8; nv++) {
        float2 a = make_float2(o[nv][0] * il, o[nv][1] * il);
        float2 c = make_float2(o[nv][2] * ih, o[nv][3] * ih);
        *(float2*)&ylo[nv*8 + 2*m] = a;
        *(float2*)&yhi[nv*8 + 2*m] = c;
    }
}

// ---------------------------------------------------------------------------
extern "C" void kernel_launch(void* const* d_in, const int* in_sizes, int n_in,
                              void* d_out, int out_size) {
    const float* x       = (const float*)d_in[0];
    const int*   pad     = (const int*)  d_in[1];
    const float* attn_w  = (const float*)d_in[2];
    const float* attn_b  = (const float*)d_in[3];
    const float* la_attn = (const float*)d_in[4];
    const float* lb_attn = (const float*)d_in[5];
    const float* proj_w  = (const float*)d_in[6];
    const float* proj_b  = (const float*)d_in[7];
    const float* la_proj = (const float*)d_in[8];
    const float* lb_proj = (const float*)d_in[9];
    float* out = (float*)d_out;

    static int smem_set = 0;
    if (!smem_set) {
        cudaFuncSetAttribute(gemm_lora_tf32<0>,
                             cudaFuncAttributeMaxDynamicSharedMemorySize, GEMM_SMEM);
        cudaFuncSetAttribute(gemm_lora_tf32<1>,
                             cudaFuncAttributeMaxDynamicSharedMemorySize, GEMM_SMEM);
        smem_set = 1;
    }

    padbits_kernel<<<MTOK, 256>>>(pad, x);               // pad bits + x_tf32 -> g_y
    lora_vec_kernel<<<MTOK, 256>>>(x, la_attn, 0);
    gemm_lora_tf32<0><<<dim3(NQKV/BN, MTOK/BM), 256, GEMM_SMEM>>>(attn_w, lb_attn, attn_b, nullptr);
    attn_mma_kernel<<<dim3(8, BB*HH), 256>>>();          // overwrites g_y with y
    lora_vec_kernel<<<MTOK, 256>>>(nullptr, la_proj, 1);
    gemm_lora_tf32<1><<<dim3(CC/BN, MTOK/BM), 256, GEMM_SMEM>>>(proj_w, lb_proj, proj_b, out);
}